// round 16
// baseline (speedup 1.0000x reference)
#include <cuda_runtime.h>
#include <cstdint>

#define NB   8
#define CCH  256
#define SP   4096
#define NROW 32768
#define KCB  1024

#define ZQ_SIZE   8388608
#define LOSS_OFF  8388608
#define PERP_OFF  8388609
#define IDX_OFF   8388610
#define FULL_OUT  8421378

#define ZSCALE   18.0f
#define ESCALE   130048.0f                 // 127*1024
#define NEG2INV  (-2.0f / (18.0f * 130048.0f))
#define MARGIN   4.0e-3f
#define CAP      32

__device__ float    g_S[NROW];
__device__ float    g_esq[KCB];
__device__ int      g_idx[NROW];
__device__ int      g_counts[KCB];
__device__ double   g_losspart[1024];
__device__ uint32_t g_e8[KCB * 64];            // packed int8 codebook (4 ch/u32)
__device__ unsigned short g_candk[NROW * CAP]; // shortlist per row
__device__ unsigned char  g_candn[NROW];       // count (CAP+1 = overflow)

__device__ __forceinline__ unsigned fkey(float f) {
    unsigned u = __float_as_uint(f);
    return (u & 0x80000000u) ? ~u : (u | 0x80000000u);
}
__device__ __forceinline__ float finv(unsigned k) {
    unsigned u = (k & 0x80000000u) ? (k & 0x7FFFFFFFu) : ~k;
    return __uint_as_float(u);
}
__device__ __forceinline__ int q8(float x, float sc) {
    float y = fminf(fmaxf(x * sc, -127.f), 127.f);
    return __float2int_rn(y);
}
__device__ __forceinline__ uint32_t pack4(int a, int b, int c, int d) {
    return (uint32_t)(a & 255) | ((uint32_t)(b & 255) << 8) |
           ((uint32_t)(c & 255) << 16) | ((uint32_t)(d & 255) << 24);
}
__device__ __forceinline__ int dp4as(uint32_t a, uint32_t b, int c) {
    return __dp4a((int)a, (int)b, c);   // signed overload, explicit
}

// ---------------------------------------------------------------------------
// Kernel A: |z|^2 per row, |e|^2 + int8-pack per code, zero counts
// ---------------------------------------------------------------------------
__global__ void prep_kernel(const float* __restrict__ z,
                            const float* __restrict__ emb) {
    int bi  = blockIdx.x;
    int tid = threadIdx.x;
    if (bi < 128) {
        int n0 = bi * 256;
        int b  = n0 >> 12;
        int s  = (n0 & 4095) + tid;
        const float* zb = z + (size_t)b * CCH * SP + s;
        float acc = 0.f;
        #pragma unroll 8
        for (int c = 0; c < CCH; c++) {
            float v = zb[(size_t)c * SP];
            acc = __fmaf_rn(v, v, acc);
        }
        g_S[n0 + tid] = acc;
    } else if (bi < 132) {
        int k = (bi - 128) * 256 + tid;
        const float* er = emb + (size_t)k * CCH;
        float acc = 0.f;
        #pragma unroll 4
        for (int j = 0; j < 64; j++) {
            float4 v = *(const float4*)(er + 4 * j);
            // exact sequential fp32 accumulation (R4-validated order)
            acc = __fmaf_rn(v.x, v.x, acc);
            acc = __fmaf_rn(v.y, v.y, acc);
            acc = __fmaf_rn(v.z, v.z, acc);
            acc = __fmaf_rn(v.w, v.w, acc);
            g_e8[(size_t)k * 64 + j] =
                pack4(q8(v.x, ESCALE), q8(v.y, ESCALE),
                      q8(v.z, ESCALE), q8(v.w, ESCALE));
        }
        g_esq[k] = acc;
    } else {
        for (int k = tid; k < KCB; k += 256) g_counts[k] = 0;
    }
}

// ---------------------------------------------------------------------------
// Kernel B: int8 dp4a filter, single pass, margin shortlist (cap 32)
//   256 threads = 16(kt) x 16(st); thread tile 8 rows x 8 codes (k stride 16)
//   zq: [64 cg][128 s] u32 (staged once, reused for all 8 k-tiles)
//   eq: [128 k][pitch 68] u32 per k-tile
// ---------------------------------------------------------------------------
#define OFF_EQ    32768                 // zq = 64*128*4
#define OFF_ESQ   67584                 // eq = 128*68*4 = 34816
#define OFF_BESTU 68096
#define OFF_CCNT  68608
#define OFF_CAND  69120                 // 128*32*2 = 8192
#define ARG_SMEM  77312

__global__ __launch_bounds__(256, 2)
void argmin_dp4a_kernel(const float* __restrict__ z) {
    extern __shared__ __align__(16) unsigned char sm[];
    uint32_t*       zq    = (uint32_t*)sm;
    uint32_t*       eq    = (uint32_t*)(sm + OFF_EQ);
    float*          esqs  = (float*)(sm + OFF_ESQ);
    unsigned*       bestu = (unsigned*)(sm + OFF_BESTU);
    unsigned*       ccnt  = (unsigned*)(sm + OFF_CCNT);
    unsigned short* cand  = (unsigned short*)(sm + OFF_CAND);

    int tid = threadIdx.x;
    int n0  = blockIdx.x * 128;
    int b   = n0 >> 12;
    int s0  = n0 & 4095;
    const float* zb = z + (size_t)b * CCH * SP + s0;

    if (tid < 128) { bestu[tid] = 0xFF800000u; ccnt[tid] = 0; }  // key(+inf)

    // stage zq once: [cg][s], quantize to int8, coalesced float4 reads
    {
        int s4 = (tid & 31) * 4;
        int cw = tid >> 5;
        #pragma unroll
        for (int p = 0; p < 8; p++) {
            int cg = cw + 8 * p;
            int c0 = cg * 4;
            float4 f0 = *(const float4*)(zb + (size_t)(c0 + 0) * SP + s4);
            float4 f1 = *(const float4*)(zb + (size_t)(c0 + 1) * SP + s4);
            float4 f2 = *(const float4*)(zb + (size_t)(c0 + 2) * SP + s4);
            float4 f3 = *(const float4*)(zb + (size_t)(c0 + 3) * SP + s4);
            uint4 o;
            o.x = pack4(q8(f0.x, ZSCALE), q8(f1.x, ZSCALE), q8(f2.x, ZSCALE), q8(f3.x, ZSCALE));
            o.y = pack4(q8(f0.y, ZSCALE), q8(f1.y, ZSCALE), q8(f2.y, ZSCALE), q8(f3.y, ZSCALE));
            o.z = pack4(q8(f0.z, ZSCALE), q8(f1.z, ZSCALE), q8(f2.z, ZSCALE), q8(f3.z, ZSCALE));
            o.w = pack4(q8(f0.w, ZSCALE), q8(f1.w, ZSCALE), q8(f2.w, ZSCALE), q8(f3.w, ZSCALE));
            *(uint4*)(zq + cg * 128 + s4) = o;
        }
    }

    int kt = tid & 15, st = tid >> 4;
    float bv[8];
    #pragma unroll
    for (int i = 0; i < 8; i++) bv[i] = __int_as_float(0x7f800000);

    for (int kt8 = 0; kt8 < 8; kt8++) {
        int k0 = kt8 * 128;
        __syncthreads();   // zq ready (1st iter) / eq consumers done (later)
        // stage eq [128 codes][68] + esqs, coalesced uint4 reads
        {
            const uint4* src = (const uint4*)(g_e8 + (size_t)k0 * 64);
            #pragma unroll
            for (int it = 0; it < 8; it++) {
                int i  = tid + 256 * it;       // 0..2047
                int r  = i >> 4, jg = i & 15;
                uint4 v = src[i];
                *(uint4*)(eq + r * 68 + jg * 4) = v;
            }
            if (tid < 128) esqs[tid] = g_esq[k0 + tid];
        }
        __syncthreads();

        // refresh cached row minima from shared
        #pragma unroll
        for (int i = 0; i < 8; i++) {
            float g = finv(bestu[st * 8 + i]);
            if (g < bv[i]) bv[i] = g;
        }

        int acc[8][8];
        #pragma unroll
        for (int i = 0; i < 8; i++)
            #pragma unroll
            for (int m = 0; m < 8; m++) acc[i][m] = 0;

        #pragma unroll 4
        for (int cg = 0; cg < 64; cg++) {
            uint32_t zr[8];
            *(uint4*)&zr[0] = *(const uint4*)(zq + cg * 128 + st * 8);
            *(uint4*)&zr[4] = *(const uint4*)(zq + cg * 128 + st * 8 + 4);
            uint32_t er[8];
            #pragma unroll
            for (int m = 0; m < 8; m++)
                er[m] = eq[(kt + 16 * m) * 68 + cg];
            #pragma unroll
            for (int i = 0; i < 8; i++)
                #pragma unroll
                for (int m = 0; m < 8; m++)
                    acc[i][m] = dp4as(zr[i], er[m], acc[i][m]);
        }

        // epilogue: v = esq - 2*m_hat; shared running min + margin appends
        #pragma unroll
        for (int i = 0; i < 8; i++) {
            int row = st * 8 + i;
            #pragma unroll
            for (int m = 0; m < 8; m++) {
                int   k = k0 + kt + 16 * m;
                float v = __fmaf_rn((float)acc[i][m], NEG2INV, esqs[kt + 16 * m]);
                if (v < bv[i]) {
                    bv[i] = v;
                    atomicMin(&bestu[row], fkey(v));
                }
                if (v <= bv[i] + MARGIN) {
                    unsigned pos = atomicAdd(&ccnt[row], 1u);
                    if (pos < CAP) cand[row * CAP + pos] = (unsigned short)k;
                }
            }
        }
    }

    __syncthreads();
    if (tid < 128) {
        unsigned c = ccnt[tid];
        int n = n0 + tid;
        g_candn[n] = (unsigned char)(c > CAP ? CAP + 1 : c);
        int mm = c > CAP ? CAP : (int)c;
        for (int j = 0; j < mm; j++)
            g_candk[(size_t)n * CAP + j] = cand[tid * CAP + j];
    }
}

// ---------------------------------------------------------------------------
// Kernel C: fused exact recheck + STE + counts + loss partials (R14-proven)
// ---------------------------------------------------------------------------
#define F_ZT   0                 // float [256][33]
#define F_ES   33792             // float [32][257]
#define F_RED  66688             // double [256]
#define F_CAND 68736             // u16 [32][CAP]
#define F_CNT  70784             // int [32]
#define F_IDX  70912             // int [32]
#define FUSE_SMEM 71040

__global__ __launch_bounds__(256)
void fuse_kernel(const float* __restrict__ z,
                 const float* __restrict__ emb,
                 float* __restrict__ out,
                 int has_extras) {
    extern __shared__ __align__(16) unsigned char sm[];
    float*          zt    = (float*)(sm + F_ZT);
    float*          es    = (float*)(sm + F_ES);
    double*         red   = (double*)(sm + F_RED);
    unsigned short* scand = (unsigned short*)(sm + F_CAND);
    int*            scnt  = (int*)(sm + F_CNT);
    int*            sidx  = (int*)(sm + F_IDX);

    int tid = threadIdx.x;
    int n0  = blockIdx.x * 32;
    int b   = n0 >> 12;
    int s0  = n0 & 4095;
    const float* zb = z + (size_t)b * CCH * SP + s0;

    // stage z tile [256 c][32 s]
    {
        int c8 = tid >> 5, s = tid & 31;
        for (int p = 0; p < 32; p++) {
            int c = p * 8 + c8;
            zt[c * 33 + s] = zb[(size_t)c * SP + s];
        }
    }
    if (tid < 32) scnt[tid] = g_candn[n0 + tid];
    for (int i = tid; i < 32 * CAP; i += 256)
        scand[i] = g_candk[(size_t)n0 * CAP + i];
    __syncthreads();

    // exact recheck: s = tid>>3 (row), cg = tid&7 (channel group of 32)
    {
        int s  = tid >> 3, cg = tid & 7;
        int n  = n0 + s;
        int cnt = scnt[s];
        unsigned segmask = 0xFFu << (tid & 24);
        if (cnt == 1) {
            if (cg == 0) { int k = scand[s * CAP]; sidx[s] = k; g_idx[n] = k; }
        } else {
            float S = g_S[n];
            bool listed = (cnt >= 2 && cnt <= CAP);
            int trips = listed ? cnt : KCB;
            unsigned long long bk = 0xFFFFFFFFFFFFFFFFULL;
            for (int i = 0; i < trips; i++) {
                int k = listed ? (int)scand[s * CAP + i] : i;
                const float4* e4 = (const float4*)(emb + (size_t)k * CCH);
                float p = 0.f;
                #pragma unroll
                for (int j4 = 0; j4 < 8; j4++) {
                    float4 ev = e4[cg * 8 + j4];
                    int c = cg * 32 + j4 * 4;
                    p = __fmaf_rn(zt[(c + 0) * 33 + s], ev.x, p);
                    p = __fmaf_rn(zt[(c + 1) * 33 + s], ev.y, p);
                    p = __fmaf_rn(zt[(c + 2) * 33 + s], ev.z, p);
                    p = __fmaf_rn(zt[(c + 3) * 33 + s], ev.w, p);
                }
                p += __shfl_down_sync(segmask, p, 4, 8);
                p += __shfl_down_sync(segmask, p, 2, 8);
                p += __shfl_down_sync(segmask, p, 1, 8);
                if (cg == 0) {
                    float t = __fadd_rn(S, g_esq[k]);
                    float v = __fmaf_rn(-2.f, p, t);
                    unsigned long long key =
                        ((unsigned long long)fkey(v) << 32) | (unsigned)k;
                    if (key < bk) bk = key;
                }
            }
            if (cg == 0) {
                int k = (int)(bk & 0xFFFFFFFFu);
                sidx[s] = k; g_idx[n] = k;
            }
        }
    }
    __syncthreads();

    // gather chosen embedding rows
    for (int i = tid; i < 32 * 64; i += 256) {
        int r = i >> 6, qq = i & 63;
        float4 v = *(const float4*)(emb + (size_t)sidx[r] * CCH + qq * 4);
        es[r * 257 + qq * 4 + 0] = v.x;
        es[r * 257 + qq * 4 + 1] = v.y;
        es[r * 257 + qq * 4 + 2] = v.z;
        es[r * 257 + qq * 4 + 3] = v.w;
    }
    if (tid < 32) atomicAdd(&g_counts[sidx[tid]], 1);
    __syncthreads();

    // STE + loss (R4-validated rounding recipe)
    int s  = tid & 31;
    int cb = tid >> 5;
    float* ob = out + (size_t)b * CCH * SP + s0;
    float lacc = 0.f;
    #pragma unroll 4
    for (int c0 = 0; c0 < CCH; c0 += 8) {
        int c = c0 + cb;
        float zv = zt[c * 33 + s];
        float ev = es[s * 257 + c];
        float dd = __fadd_rn(ev, -zv);
        lacc = __fmaf_rn(dd, dd, lacc);
        ob[(size_t)c * SP + s] = __fadd_rn(zv, dd);
    }
    if (has_extras && tid < 32)
        out[IDX_OFF + n0 + tid] = (float)sidx[tid];

    red[tid] = (double)lacc;
    __syncthreads();
    for (int off = 128; off > 0; off >>= 1) {
        if (tid < off) red[tid] += red[tid + off];
        __syncthreads();
    }
    if (tid == 0) g_losspart[blockIdx.x] = red[0];
}

// ---------------------------------------------------------------------------
// Kernel D: final loss + perplexity (unchanged, R4-validated)
// ---------------------------------------------------------------------------
__global__ __launch_bounds__(1024)
void finalize_kernel(float* __restrict__ out, int has_extras) {
    __shared__ double sd[1024];
    int tid = threadIdx.x;

    {
        int   cnt = g_counts[tid];
        float em  = (float)cnt * (1.0f / 32768.0f);
        float t   = em * logf(em + 1e-10f);
        sd[tid] = (double)t;
    }
    __syncthreads();
    for (int off = 512; off > 0; off >>= 1) {
        if (tid < off) sd[tid] += sd[tid + off];
        __syncthreads();
    }
    float perplexity = expf(-(float)sd[0]);
    __syncthreads();

    sd[tid] = g_losspart[tid];
    __syncthreads();
    for (int off = 512; off > 0; off >>= 1) {
        if (tid < off) sd[tid] += sd[tid + off];
        __syncthreads();
    }
    if (tid == 0 && has_extras) {
        double mean = sd[0] / (double)ZQ_SIZE;
        float  m    = (float)mean;
        float  loss = __fadd_rn(m, 0.25f * m);
        out[LOSS_OFF] = loss;
        out[PERP_OFF] = perplexity;
    }
}

// ---------------------------------------------------------------------------
extern "C" void kernel_launch(void* const* d_in, const int* in_sizes, int n_in,
                              void* d_out, int out_size) {
    const float* z   = (const float*)d_in[0];
    const float* emb = (const float*)d_in[1];
    float* out = (float*)d_out;
    int has_extras = (out_size >= FULL_OUT) ? 1 : 0;

    cudaFuncSetAttribute(argmin_dp4a_kernel,
                         cudaFuncAttributeMaxDynamicSharedMemorySize, ARG_SMEM);
    cudaFuncSetAttribute(fuse_kernel,
                         cudaFuncAttributeMaxDynamicSharedMemorySize, FUSE_SMEM);

    prep_kernel<<<133, 256>>>(z, emb);
    argmin_dp4a_kernel<<<NROW / 128, 256, ARG_SMEM>>>(z);
    fuse_kernel<<<NROW / 32, 256, FUSE_SMEM>>>(z, emb, out, has_extras);
    finalize_kernel<<<1, 1024>>>(out, has_extras);
}

// round 17
// speedup vs baseline: 39.0426x; 39.0426x over previous
#include <cuda_runtime.h>
#include <cstdint>

#define NB   8
#define CCH  256
#define SP   4096
#define NROW 32768
#define KCB  1024

#define ZQ_SIZE   8388608
#define LOSS_OFF  8388608
#define PERP_OFF  8388609
#define IDX_OFF   8388610
#define FULL_OUT  8421378

#define ZSCALE   18.0f
#define ESCALE   130048.0f                 // 127*1024
#define NEG2INV  (-2.0f / (18.0f * 130048.0f))
#define MARGIN   4.0e-3f
#define CAP      32        // in-kernel append cap
#define CAPG     16        // post-prune survivor cap (global)

__device__ float    g_S[NROW];
__device__ float    g_esq[KCB];
__device__ int      g_idx[NROW];
__device__ int      g_counts[KCB];
__device__ double   g_losspart[1024];
__device__ uint32_t g_e8[KCB * 64];             // packed int8 codebook (4 ch/u32)
__device__ unsigned short g_candk[NROW * CAPG]; // pruned shortlist per row
__device__ unsigned char  g_candn[NROW];        // count (CAPG+1 = overflow)

__device__ __forceinline__ unsigned fkey(float f) {
    unsigned u = __float_as_uint(f);
    return (u & 0x80000000u) ? ~u : (u | 0x80000000u);
}
__device__ __forceinline__ float finv(unsigned k) {
    unsigned u = (k & 0x80000000u) ? (k & 0x7FFFFFFFu) : ~k;
    return __uint_as_float(u);
}
__device__ __forceinline__ int q8(float x, float sc) {
    float y = fminf(fmaxf(x * sc, -127.f), 127.f);
    return __float2int_rn(y);
}
__device__ __forceinline__ uint32_t pack4(int a, int b, int c, int d) {
    return (uint32_t)(a & 255) | ((uint32_t)(b & 255) << 8) |
           ((uint32_t)(c & 255) << 16) | ((uint32_t)(d & 255) << 24);
}
__device__ __forceinline__ int dp4as(uint32_t a, uint32_t b, int c) {
    return __dp4a((int)a, (int)b, c);   // signed overload, explicit
}

// ---------------------------------------------------------------------------
// Kernel A: |z|^2 per row, |e|^2 + int8-pack per code, zero counts
// ---------------------------------------------------------------------------
__global__ void prep_kernel(const float* __restrict__ z,
                            const float* __restrict__ emb) {
    int bi  = blockIdx.x;
    int tid = threadIdx.x;
    if (bi < 128) {
        int n0 = bi * 256;
        int b  = n0 >> 12;
        int s  = (n0 & 4095) + tid;
        const float* zb = z + (size_t)b * CCH * SP + s;
        float acc = 0.f;
        #pragma unroll 8
        for (int c = 0; c < CCH; c++) {
            float v = zb[(size_t)c * SP];
            acc = __fmaf_rn(v, v, acc);
        }
        g_S[n0 + tid] = acc;
    } else if (bi < 132) {
        int k = (bi - 128) * 256 + tid;
        const float* er = emb + (size_t)k * CCH;
        float acc = 0.f;
        #pragma unroll 4
        for (int j = 0; j < 64; j++) {
            float4 v = *(const float4*)(er + 4 * j);
            acc = __fmaf_rn(v.x, v.x, acc);
            acc = __fmaf_rn(v.y, v.y, acc);
            acc = __fmaf_rn(v.z, v.z, acc);
            acc = __fmaf_rn(v.w, v.w, acc);
            g_e8[(size_t)k * 64 + j] =
                pack4(q8(v.x, ESCALE), q8(v.y, ESCALE),
                      q8(v.z, ESCALE), q8(v.w, ESCALE));
        }
        g_esq[k] = acc;
    } else {
        for (int k = tid; k < KCB; k += 256) g_counts[k] = 0;
    }
}

// ---------------------------------------------------------------------------
// Kernel B: int8 dp4a filter, single sweep.
//   Per tile: compute 64 dists/thread -> half-warp min reduce -> shared
//   atomicMin -> sync -> append vs THROUGH-TILE min (superset of final
//   margin set). At exit: prune to final_min+MARGIN in exact key space.
// ---------------------------------------------------------------------------
#define OFF_EQ    32768                 // zq = 64*128*4
#define OFF_ESQ   67584                 // eq = 128*68*4 = 34816
#define OFF_BESTU 68096
#define OFF_CCNT  68608
#define OFF_CANDK 69120                 // u16 [128*CAP] = 8192
#define OFF_CANDF 77312                 // u32 [128*CAP] = 16384
#define ARG_SMEM  93696

__global__ __launch_bounds__(256, 2)
void argmin_dp4a_kernel(const float* __restrict__ z) {
    extern __shared__ __align__(16) unsigned char sm[];
    uint32_t*       zq    = (uint32_t*)sm;
    uint32_t*       eq    = (uint32_t*)(sm + OFF_EQ);
    float*          esqs  = (float*)(sm + OFF_ESQ);
    unsigned*       bestu = (unsigned*)(sm + OFF_BESTU);
    unsigned*       ccnt  = (unsigned*)(sm + OFF_CCNT);
    unsigned short* candk = (unsigned short*)(sm + OFF_CANDK);
    unsigned*       candf = (unsigned*)(sm + OFF_CANDF);

    int tid = threadIdx.x;
    int n0  = blockIdx.x * 128;
    int b   = n0 >> 12;
    int s0  = n0 & 4095;
    const float* zb = z + (size_t)b * CCH * SP + s0;

    if (tid < 128) { bestu[tid] = 0xFF800000u; ccnt[tid] = 0; }  // key(+inf)

    // stage zq once: [cg][s], int8 quantized, coalesced float4 reads
    {
        int s4 = (tid & 31) * 4;
        int cw = tid >> 5;
        #pragma unroll
        for (int p = 0; p < 8; p++) {
            int cg = cw + 8 * p;
            int c0 = cg * 4;
            float4 f0 = *(const float4*)(zb + (size_t)(c0 + 0) * SP + s4);
            float4 f1 = *(const float4*)(zb + (size_t)(c0 + 1) * SP + s4);
            float4 f2 = *(const float4*)(zb + (size_t)(c0 + 2) * SP + s4);
            float4 f3 = *(const float4*)(zb + (size_t)(c0 + 3) * SP + s4);
            uint4 o;
            o.x = pack4(q8(f0.x, ZSCALE), q8(f1.x, ZSCALE), q8(f2.x, ZSCALE), q8(f3.x, ZSCALE));
            o.y = pack4(q8(f0.y, ZSCALE), q8(f1.y, ZSCALE), q8(f2.y, ZSCALE), q8(f3.y, ZSCALE));
            o.z = pack4(q8(f0.z, ZSCALE), q8(f1.z, ZSCALE), q8(f2.z, ZSCALE), q8(f3.z, ZSCALE));
            o.w = pack4(q8(f0.w, ZSCALE), q8(f1.w, ZSCALE), q8(f2.w, ZSCALE), q8(f3.w, ZSCALE));
            *(uint4*)(zq + cg * 128 + s4) = o;
        }
    }

    int kt = tid & 15, st = tid >> 4;

    for (int kt8 = 0; kt8 < 8; kt8++) {
        int k0 = kt8 * 128;
        __syncthreads();   // zq ready (1st) / previous-tile consumers done
        // stage eq [128 codes][pitch 68] + esqs
        {
            const uint4* src = (const uint4*)(g_e8 + (size_t)k0 * 64);
            #pragma unroll
            for (int it = 0; it < 8; it++) {
                int i  = tid + 256 * it;
                int r  = i >> 4, jg = i & 15;
                uint4 v = src[i];
                *(uint4*)(eq + r * 68 + jg * 4) = v;
            }
            if (tid < 128) esqs[tid] = g_esq[k0 + tid];
        }
        __syncthreads();

        int acc[8][8];
        #pragma unroll
        for (int i = 0; i < 8; i++)
            #pragma unroll
            for (int m = 0; m < 8; m++) acc[i][m] = 0;

        #pragma unroll 4
        for (int cg = 0; cg < 64; cg++) {
            uint32_t zr[8];
            *(uint4*)&zr[0] = *(const uint4*)(zq + cg * 128 + st * 8);
            *(uint4*)&zr[4] = *(const uint4*)(zq + cg * 128 + st * 8 + 4);
            uint32_t er[8];
            #pragma unroll
            for (int m = 0; m < 8; m++)
                er[m] = eq[(kt + 16 * m) * 68 + cg];
            #pragma unroll
            for (int i = 0; i < 8; i++)
                #pragma unroll
                for (int m = 0; m < 8; m++)
                    acc[i][m] = dp4as(zr[i], er[m], acc[i][m]);
        }

        // distances + per-row tile min (half-warp reduce, width 16)
        float vv[8][8];
        #pragma unroll
        for (int i = 0; i < 8; i++) {
            float lm = __int_as_float(0x7f800000);
            #pragma unroll
            for (int m = 0; m < 8; m++) {
                float v = __fmaf_rn((float)acc[i][m], NEG2INV, esqs[kt + 16 * m]);
                vv[i][m] = v;
                if (v < lm) lm = v;
            }
            #pragma unroll
            for (int j = 8; j > 0; j >>= 1)
                lm = fminf(lm, __shfl_xor_sync(0xFFFFFFFFu, lm, j, 16));
            if (kt == 0) atomicMin(&bestu[st * 8 + i], fkey(lm));
        }
        __syncthreads();   // through-tile mins visible

        // append vs through-tile min (superset of final-margin set)
        #pragma unroll
        for (int i = 0; i < 8; i++) {
            int row = st * 8 + i;
            float lim = finv(bestu[row]) + MARGIN;
            #pragma unroll
            for (int m = 0; m < 8; m++) {
                if (vv[i][m] <= lim) {
                    int k = k0 + kt + 16 * m;
                    unsigned pos = atomicAdd(&ccnt[row], 1u);
                    if (pos < CAP) {
                        candk[row * CAP + pos] = (unsigned short)k;
                        candf[row * CAP + pos] = fkey(vv[i][m]);
                    }
                }
            }
        }
    }

    __syncthreads();
    // exit prune: keep only v <= final_min + MARGIN (exact in key space)
    if (tid < 128) {
        int n = n0 + tid;
        unsigned c  = ccnt[tid];
        if (c > CAP) {
            g_candn[n] = (unsigned char)(CAPG + 1);   // overflow -> exhaustive
        } else {
            unsigned thr = fkey(finv(bestu[tid]) + MARGIN);
            int m = 0;
            for (int j = 0; j < (int)c; j++) {
                if (candf[tid * CAP + j] <= thr) {
                    if (m < CAPG) g_candk[(size_t)n * CAPG + m] = candk[tid * CAP + j];
                    m++;
                }
            }
            g_candn[n] = (unsigned char)(m > CAPG ? CAPG + 1 : m);
        }
    }
}

// ---------------------------------------------------------------------------
// Kernel C: fused exact recheck + STE + counts + loss partials (R14-proven)
// ---------------------------------------------------------------------------
#define F_ZT   0                 // float [256][33]
#define F_ES   33792             // float [32][257]
#define F_RED  66688             // double [256]
#define F_CAND 68736             // u16 [32][CAPG]
#define F_CNT  69760             // int [32]
#define F_IDX  69888             // int [32]
#define FUSE_SMEM 70016

__global__ __launch_bounds__(256)
void fuse_kernel(const float* __restrict__ z,
                 const float* __restrict__ emb,
                 float* __restrict__ out,
                 int has_extras) {
    extern __shared__ __align__(16) unsigned char sm[];
    float*          zt    = (float*)(sm + F_ZT);
    float*          es    = (float*)(sm + F_ES);
    double*         red   = (double*)(sm + F_RED);
    unsigned short* scand = (unsigned short*)(sm + F_CAND);
    int*            scnt  = (int*)(sm + F_CNT);
    int*            sidx  = (int*)(sm + F_IDX);

    int tid = threadIdx.x;
    int n0  = blockIdx.x * 32;
    int b   = n0 >> 12;
    int s0  = n0 & 4095;
    const float* zb = z + (size_t)b * CCH * SP + s0;

    // stage z tile [256 c][32 s]
    {
        int c8 = tid >> 5, s = tid & 31;
        for (int p = 0; p < 32; p++) {
            int c = p * 8 + c8;
            zt[c * 33 + s] = zb[(size_t)c * SP + s];
        }
    }
    if (tid < 32) scnt[tid] = g_candn[n0 + tid];
    for (int i = tid; i < 32 * CAPG; i += 256)
        scand[i] = g_candk[(size_t)n0 * CAPG + i];
    __syncthreads();

    // exact recheck: s = tid>>3 (row), cg = tid&7 (channel group of 32)
    {
        int s  = tid >> 3, cg = tid & 7;
        int n  = n0 + s;
        int cnt = scnt[s];
        unsigned segmask = 0xFFu << (tid & 24);
        if (cnt == 1) {
            if (cg == 0) { int k = scand[s * CAPG]; sidx[s] = k; g_idx[n] = k; }
        } else {
            float S = g_S[n];
            bool listed = (cnt >= 2 && cnt <= CAPG);
            int trips = listed ? cnt : KCB;
            unsigned long long bk = 0xFFFFFFFFFFFFFFFFULL;
            for (int i = 0; i < trips; i++) {
                int k = listed ? (int)scand[s * CAPG + i] : i;
                const float4* e4 = (const float4*)(emb + (size_t)k * CCH);
                float p = 0.f;
                #pragma unroll
                for (int j4 = 0; j4 < 8; j4++) {
                    float4 ev = e4[cg * 8 + j4];
                    int c = cg * 32 + j4 * 4;
                    p = __fmaf_rn(zt[(c + 0) * 33 + s], ev.x, p);
                    p = __fmaf_rn(zt[(c + 1) * 33 + s], ev.y, p);
                    p = __fmaf_rn(zt[(c + 2) * 33 + s], ev.z, p);
                    p = __fmaf_rn(zt[(c + 3) * 33 + s], ev.w, p);
                }
                p += __shfl_down_sync(segmask, p, 4, 8);
                p += __shfl_down_sync(segmask, p, 2, 8);
                p += __shfl_down_sync(segmask, p, 1, 8);
                if (cg == 0) {
                    float t = __fadd_rn(S, g_esq[k]);
                    float v = __fmaf_rn(-2.f, p, t);
                    unsigned long long key =
                        ((unsigned long long)fkey(v) << 32) | (unsigned)k;
                    if (key < bk) bk = key;
                }
            }
            if (cg == 0) {
                int k = (int)(bk & 0xFFFFFFFFu);
                sidx[s] = k; g_idx[n] = k;
            }
        }
    }
    __syncthreads();

    // gather chosen embedding rows
    for (int i = tid; i < 32 * 64; i += 256) {
        int r = i >> 6, qq = i & 63;
        float4 v = *(const float4*)(emb + (size_t)sidx[r] * CCH + qq * 4);
        es[r * 257 + qq * 4 + 0] = v.x;
        es[r * 257 + qq * 4 + 1] = v.y;
        es[r * 257 + qq * 4 + 2] = v.z;
        es[r * 257 + qq * 4 + 3] = v.w;
    }
    if (tid < 32) atomicAdd(&g_counts[sidx[tid]], 1);
    __syncthreads();

    // STE + loss (R4-validated rounding recipe)
    int s  = tid & 31;
    int cb = tid >> 5;
    float* ob = out + (size_t)b * CCH * SP + s0;
    float lacc = 0.f;
    #pragma unroll 4
    for (int c0 = 0; c0 < CCH; c0 += 8) {
        int c = c0 + cb;
        float zv = zt[c * 33 + s];
        float ev = es[s * 257 + c];
        float dd = __fadd_rn(ev, -zv);
        lacc = __fmaf_rn(dd, dd, lacc);
        ob[(size_t)c * SP + s] = __fadd_rn(zv, dd);
    }
    if (has_extras && tid < 32)
        out[IDX_OFF + n0 + tid] = (float)sidx[tid];

    red[tid] = (double)lacc;
    __syncthreads();
    for (int off = 128; off > 0; off >>= 1) {
        if (tid < off) red[tid] += red[tid + off];
        __syncthreads();
    }
    if (tid == 0) g_losspart[blockIdx.x] = red[0];
}

// ---------------------------------------------------------------------------
// Kernel D: final loss + perplexity (unchanged, R4-validated)
// ---------------------------------------------------------------------------
__global__ __launch_bounds__(1024)
void finalize_kernel(float* __restrict__ out, int has_extras) {
    __shared__ double sd[1024];
    int tid = threadIdx.x;

    {
        int   cnt = g_counts[tid];
        float em  = (float)cnt * (1.0f / 32768.0f);
        float t   = em * logf(em + 1e-10f);
        sd[tid] = (double)t;
    }
    __syncthreads();
    for (int off = 512; off > 0; off >>= 1) {
        if (tid < off) sd[tid] += sd[tid + off];
        __syncthreads();
    }
    float perplexity = expf(-(float)sd[0]);
    __syncthreads();

    sd[tid] = g_losspart[tid];
    __syncthreads();
    for (int off = 512; off > 0; off >>= 1) {
        if (tid < off) sd[tid] += sd[tid + off];
        __syncthreads();
    }
    if (tid == 0 && has_extras) {
        double mean = sd[0] / (double)ZQ_SIZE;
        float  m    = (float)mean;
        float  loss = __fadd_rn(m, 0.25f * m);
        out[LOSS_OFF] = loss;
        out[PERP_OFF] = perplexity;
    }
}

// ---------------------------------------------------------------------------
extern "C" void kernel_launch(void* const* d_in, const int* in_sizes, int n_in,
                              void* d_out, int out_size) {
    const float* z   = (const float*)d_in[0];
    const float* emb = (const float*)d_in[1];
    float* out = (float*)d_out;
    int has_extras = (out_size >= FULL_OUT) ? 1 : 0;

    cudaFuncSetAttribute(argmin_dp4a_kernel,
                         cudaFuncAttributeMaxDynamicSharedMemorySize, ARG_SMEM);
    cudaFuncSetAttribute(fuse_kernel,
                         cudaFuncAttributeMaxDynamicSharedMemorySize, FUSE_SMEM);

    prep_kernel<<<133, 256>>>(z, emb);
    argmin_dp4a_kernel<<<NROW / 128, 256, ARG_SMEM>>>(z);
    fuse_kernel<<<NROW / 32, 256, FUSE_SMEM>>>(z, emb, out, has_extras);
    finalize_kernel<<<1, 1024>>>(out, has_extras);
}